// round 6
// baseline (speedup 1.0000x reference)
#include <cuda_runtime.h>

#define HIDDEN 32
#define FEAT 30
#define NK 29                 /* feature 29 (mask bit) folded into bias */
#define TSTEPS 512
#define BATCH 4096
#define CHUNK 16
#define FULLMASK 0xffffffffu

typedef unsigned long long ull;

__device__ __forceinline__ float tanhap(float x) {
    float y; asm("tanh.approx.f32 %0, %1;" : "=f"(y) : "f"(x)); return y;
}
__device__ __forceinline__ float sigf(float x) {
    return fmaf(0.5f, tanhap(0.5f * x), 0.5f);
}
__device__ __forceinline__ ull fma2(ull a, ull b, ull c) {
    ull d;
    asm("fma.rn.f32x2 %0, %1, %2, %3;" : "=l"(d) : "l"(a), "l"(b), "l"(c));
    return d;
}
__device__ __forceinline__ ull pack2(float lo, float hi) {
    ull d; asm("mov.b64 %0, {%1, %2};" : "=l"(d) : "f"(lo), "f"(hi)); return d;
}
__device__ __forceinline__ ull dup2(float v) {
    ull d; asm("mov.b64 %0, {%1, %1};" : "=l"(d) : "f"(v)); return d;
}
__device__ __forceinline__ float2 unpack2(ull v) {
    float lo, hi; asm("mov.b64 {%0, %1}, %2;" : "=f"(lo), "=f"(hi) : "l"(v));
    return make_float2(lo, hi);
}

struct Smem {
    ulonglong2 sWih[NK][HIDDEN];     // [k][j] = ((w_i,w_f),(w_g,w_o)), k<29
    ull        sWgo[HIDDEN][HIDDEN]; // [k][j] = (whh_g, whh_o)  lane-distinct LDS.64
    ulonglong2 xq[2][HIDDEN];        // [buf][k] = ((xA,xB),(xC,xD))
    ulonglong2 hq[2][HIDDEN];        // [buf][j] = ((hA,hB),(hC,hD))
    ulonglong2 hist[CHUNK][33];      // [slot][j] = masked h, padded
    ull wcd0[HIDDEN], wcd1[HIDDEN], wcdl[HIDDEN];
};

__global__ void __launch_bounds__(32)
lstm_fused_kernel(
    const float* __restrict__ x, const float* __restrict__ h0, const float* __restrict__ c0,
    const float* __restrict__ W_ih, const float* __restrict__ W_hh,
    const float* __restrict__ b_ih, const float* __restrict__ b_hh,
    const float* __restrict__ W_all, const float* __restrict__ b_all,
    const float* __restrict__ W_pos, const float* __restrict__ b_pos,
    const float* __restrict__ W_lv, const float* __restrict__ b_lv,
    float* __restrict__ out)
{
    __shared__ Smem sm;
    const int lane = threadIdx.x;
    const int s0 = blockIdx.x * 4;

    // ---- one-time init ----
    #pragma unroll
    for (int k = 0; k < NK; ++k) {
        sm.sWih[k][lane] = make_ulonglong2(
            pack2(W_ih[lane * FEAT + k],        W_ih[(32 + lane) * FEAT + k]),
            pack2(W_ih[(64 + lane) * FEAT + k], W_ih[(96 + lane) * FEAT + k]));
    }
    // W_hh: (i,f) pairs register-resident; (g,o) pairs in smem.
    ull whh_if[HIDDEN];
    #pragma unroll
    for (int k = 0; k < HIDDEN; ++k) {
        whh_if[k] = pack2(W_hh[lane * HIDDEN + k], W_hh[(32 + lane) * HIDDEN + k]);
        sm.sWgo[k][lane] = pack2(W_hh[(64 + lane) * HIDDEN + k],
                                 W_hh[(96 + lane) * HIDDEN + k]);
    }
    // folded heads: wc = W_pos @ W_all, cb = W_pos @ b_all + b_pos
    float wc0 = 0.f, wc1 = 0.f, cb0 = b_pos[0], cb1 = b_pos[1];
    #pragma unroll
    for (int m = 0; m < HIDDEN; ++m) {
        const float wa = W_all[m * HIDDEN + lane];
        wc0 = fmaf(W_pos[m],      wa, wc0);
        wc1 = fmaf(W_pos[32 + m], wa, wc1);
        cb0 = fmaf(W_pos[m],      b_all[m], cb0);
        cb1 = fmaf(W_pos[32 + m], b_all[m], cb1);
    }
    sm.wcd0[lane] = dup2(wc0);
    sm.wcd1[lane] = dup2(wc1);
    sm.wcdl[lane] = dup2(W_lv[lane]);
    const float blv = b_lv[0];

    // Gate biases with W_ih[:,29]*1.0 folded in (mask bit is 1.0 on active steps;
    // inactive samples compute garbage gates but are selected away).
    const ull bias_if = pack2(b_ih[lane]      + b_hh[lane]      + W_ih[lane * FEAT + 29],
                              b_ih[32 + lane] + b_hh[32 + lane] + W_ih[(32 + lane) * FEAT + 29]);
    const ull bias_go = pack2(b_ih[64 + lane] + b_hh[64 + lane] + W_ih[(64 + lane) * FEAT + 29],
                              b_ih[96 + lane] + b_hh[96 + lane] + W_ih[(96 + lane) * FEAT + 29]);

    const float* xA = x + (size_t)(s0 + 0) * TSTEPS * FEAT;
    const float* xB = x + (size_t)(s0 + 1) * TSTEPS * FEAT;
    const float* xC = x + (size_t)(s0 + 2) * TSTEPS * FEAT;
    const float* xD = x + (size_t)(s0 + 3) * TSTEPS * FEAT;

    float hA = h0[(s0 + 0) * HIDDEN + lane], cA = c0[(s0 + 0) * HIDDEN + lane];
    float hB = h0[(s0 + 1) * HIDDEN + lane], cB = c0[(s0 + 1) * HIDDEN + lane];
    float hC = h0[(s0 + 2) * HIDDEN + lane], cC = c0[(s0 + 2) * HIDDEN + lane];
    float hD = h0[(s0 + 3) * HIDDEN + lane], cD = c0[(s0 + 3) * HIDDEN + lane];

    sm.hq[0][lane] = make_ulonglong2(pack2(hA, hB), pack2(hC, hD));
    sm.xq[0][lane] = make_ulonglong2(pack2(xA[lane], xB[lane]), pack2(xC[lane], xD[lane]));
    __syncwarp();

    float* pos_out = out;                                   // [B,T,2]
    float* lv_out  = out + (size_t)BATCH * TSTEPS * 2;      // [B,T,1]
    float* hT_out  = out + (size_t)BATCH * TSTEPS * 3;      // [1,B,H]
    float* cT_out  = hT_out + BATCH * HIDDEN;               // [1,B,H]

    for (int t = 0; t < TSTEPS; ++t) {
        const int bsel = t & 1;
        const int slot = t & (CHUNK - 1);

        // Unconditional prefetch (clamped at the tail; always in-bounds).
        const int tn = (t + 1 < TSTEPS) ? (t + 1) : t;
        const int o = tn * FEAT + lane;
        const float xnA = xA[o], xnB = xB[o], xnC = xC[o], xnD = xD[o];

        const ulonglong2 mq = sm.xq[bsel][FEAT - 1];
        const float2 mAB = unpack2(mq.x), mCD = unpack2(mq.y);
        const bool aA = (mAB.x == 1.0f), aB = (mAB.y == 1.0f);
        const bool aC = (mCD.x == 1.0f), aD = (mCD.y == 1.0f);

        ull ifA = bias_if, goA = bias_go, ifB = bias_if, goB = bias_go;
        ull ifC = bias_if, goC = bias_go, ifD = bias_if, goD = bias_go;
        #pragma unroll
        for (int k = 0; k < NK; ++k) {
            const ulonglong2 xk = sm.xq[bsel][k];
            const float2 uab = unpack2(xk.x), ucd = unpack2(xk.y);
            const ulonglong2 w = sm.sWih[k][lane];
            const ull vA = dup2(uab.x), vB = dup2(uab.y);
            const ull vC = dup2(ucd.x), vD = dup2(ucd.y);
            ifA = fma2(vA, w.x, ifA); goA = fma2(vA, w.y, goA);
            ifB = fma2(vB, w.x, ifB); goB = fma2(vB, w.y, goB);
            ifC = fma2(vC, w.x, ifC); goC = fma2(vC, w.y, goC);
            ifD = fma2(vD, w.x, ifD); goD = fma2(vD, w.y, goD);
        }
        #pragma unroll
        for (int k = 0; k < HIDDEN; ++k) {
            const ulonglong2 hk = sm.hq[bsel][k];
            const float2 uab = unpack2(hk.x), ucd = unpack2(hk.y);
            const ull wi = whh_if[k];
            const ull wg = sm.sWgo[k][lane];
            const ull vA = dup2(uab.x), vB = dup2(uab.y);
            const ull vC = dup2(ucd.x), vD = dup2(ucd.y);
            ifA = fma2(vA, wi, ifA); goA = fma2(vA, wg, goA);
            ifB = fma2(vB, wi, ifB); goB = fma2(vB, wg, goB);
            ifC = fma2(vC, wi, ifC); goC = fma2(vC, wg, goC);
            ifD = fma2(vD, wi, ifD); goD = fma2(vD, wg, goD);
        }

        float hsA, hsB, hsC, hsD;
        {
            const float2 g1 = unpack2(ifA), g2 = unpack2(goA);
            const float cn = fmaf(sigf(g1.y), cA, sigf(g1.x) * tanhap(g2.x));
            const float hn = sigf(g2.y) * tanhap(cn);
            cA = aA ? cn : cA; hA = aA ? hn : hA; hsA = aA ? hn : 0.f;
        }
        {
            const float2 g1 = unpack2(ifB), g2 = unpack2(goB);
            const float cn = fmaf(sigf(g1.y), cB, sigf(g1.x) * tanhap(g2.x));
            const float hn = sigf(g2.y) * tanhap(cn);
            cB = aB ? cn : cB; hB = aB ? hn : hB; hsB = aB ? hn : 0.f;
        }
        {
            const float2 g1 = unpack2(ifC), g2 = unpack2(goC);
            const float cn = fmaf(sigf(g1.y), cC, sigf(g1.x) * tanhap(g2.x));
            const float hn = sigf(g2.y) * tanhap(cn);
            cC = aC ? cn : cC; hC = aC ? hn : hC; hsC = aC ? hn : 0.f;
        }
        {
            const float2 g1 = unpack2(ifD), g2 = unpack2(goD);
            const float cn = fmaf(sigf(g1.y), cD, sigf(g1.x) * tanhap(g2.x));
            const float hn = sigf(g2.y) * tanhap(cn);
            cD = aD ? cn : cD; hD = aD ? hn : hD; hsD = aD ? hn : 0.f;
        }

        sm.hq[bsel ^ 1][lane] = make_ulonglong2(pack2(hA, hB), pack2(hC, hD));
        sm.hist[slot][lane]   = make_ulonglong2(pack2(hsA, hsB), pack2(hsC, hsD));
        sm.xq[bsel ^ 1][lane] = make_ulonglong2(pack2(xnA, xnB), pack2(xnC, xnD));
        __syncwarp();

        // bulk head phase over the finished 16-step chunk
        if (slot == CHUNK - 1) {
            const int tt = lane & 15;
            const int pr = lane >> 4;
            const ull* hrow = reinterpret_cast<const ull*>(&sm.hist[tt][0]) + pr;
            ull p0 = 0ULL, p1 = 0ULL, pl = 0ULL;
            #pragma unroll
            for (int j = 0; j < HIDDEN; ++j) {
                const ull hv = hrow[j * 2];
                p0 = fma2(hv, sm.wcd0[j], p0);
                p1 = fma2(hv, sm.wcd1[j], p1);
                pl = fma2(hv, sm.wcdl[j], pl);
            }
            const float2 q0 = unpack2(p0), q1 = unpack2(p1), ql = unpack2(pl);
            const int tg = t - (CHUNK - 1) + tt;
            const size_t oA = (size_t)(s0 + pr * 2) * TSTEPS + tg;
            const size_t oB = oA + TSTEPS;
            reinterpret_cast<float2*>(pos_out)[oA] = make_float2(q0.x + cb0, q1.x + cb1);
            reinterpret_cast<float2*>(pos_out)[oB] = make_float2(q0.y + cb0, q1.y + cb1);
            lv_out[oA] = sigf(ql.x + blv);
            lv_out[oB] = sigf(ql.y + blv);
            __syncwarp();
        }
    }

    hT_out[(s0 + 0) * HIDDEN + lane] = hA;
    hT_out[(s0 + 1) * HIDDEN + lane] = hB;
    hT_out[(s0 + 2) * HIDDEN + lane] = hC;
    hT_out[(s0 + 3) * HIDDEN + lane] = hD;
    cT_out[(s0 + 0) * HIDDEN + lane] = cA;
    cT_out[(s0 + 1) * HIDDEN + lane] = cB;
    cT_out[(s0 + 2) * HIDDEN + lane] = cC;
    cT_out[(s0 + 3) * HIDDEN + lane] = cD;
}

extern "C" void kernel_launch(void* const* d_in, const int* in_sizes, int n_in,
                              void* d_out, int out_size)
{
    const float* x    = (const float*)d_in[0];
    const float* h0   = (const float*)d_in[1];
    const float* c0   = (const float*)d_in[2];
    const float* W_ih = (const float*)d_in[3];
    const float* W_hh = (const float*)d_in[4];
    const float* b_ih = (const float*)d_in[5];
    const float* b_hh = (const float*)d_in[6];
    const float* W_all= (const float*)d_in[7];
    const float* b_all= (const float*)d_in[8];
    const float* W_pos= (const float*)d_in[9];
    const float* b_pos= (const float*)d_in[10];
    const float* W_lv = (const float*)d_in[11];
    const float* b_lv = (const float*)d_in[12];
    float* out = (float*)d_out;

    lstm_fused_kernel<<<BATCH / 4, 32>>>(x, h0, c0, W_ih, W_hh, b_ih, b_hh,
                                         W_all, b_all, W_pos, b_pos, W_lv, b_lv, out);
}

// round 8
// speedup vs baseline: 1.3953x; 1.3953x over previous
#include <cuda_runtime.h>

#define HIDDEN 32
#define FEAT 30
#define NK 29                 /* feature 29 (mask bit) folded into bias */
#define TSTEPS 512
#define BATCH 4096
#define NS 8                  /* samples per warp */
#define CHUNK 16
#define HSTRIDE 134           /* ull row stride: 134*8=1072 ≡ 0 mod 16 (STS.128-safe) */
#define TSF (TSTEPS * FEAT)

typedef unsigned long long ull;

__device__ __forceinline__ float tanhap(float x) {
    float y; asm("tanh.approx.f32 %0, %1;" : "=f"(y) : "f"(x)); return y;
}
__device__ __forceinline__ float sigf(float x) {
    return fmaf(0.5f, tanhap(0.5f * x), 0.5f);
}
__device__ __forceinline__ ull fma2(ull a, ull b, ull c) {
    ull d;
    asm("fma.rn.f32x2 %0, %1, %2, %3;" : "=l"(d) : "l"(a), "l"(b), "l"(c));
    return d;
}
__device__ __forceinline__ ull pack2(float lo, float hi) {
    ull d; asm("mov.b64 %0, {%1, %2};" : "=l"(d) : "f"(lo), "f"(hi)); return d;
}
__device__ __forceinline__ ull dup2(float v) {
    ull d; asm("mov.b64 %0, {%1, %1};" : "=l"(d) : "f"(v)); return d;
}
__device__ __forceinline__ float2 unpack2(ull v) {
    float lo, hi; asm("mov.b64 {%0, %1}, %2;" : "=f"(lo), "=f"(hi) : "l"(v));
    return make_float2(lo, hi);
}

struct Smem {
    ulonglong2 sWih[NK][HIDDEN];      // [k][j] = ((w_i,w_f),(w_g,w_o))
    ulonglong2 xq[2][HIDDEN][5];      // [buf][k][q(0..3)+pad] dup'd x, 2 samples/entry
    ulonglong2 hq[2][HIDDEN][5];      // [buf][j][q+pad] dup'd h
    ull        hist[CHUNK][HSTRIDE];  // [slot][j*4 + pr] masked-h sample pairs
    ull        wcd0[HIDDEN], wcd1[HIDDEN], wcdl[HIDDEN];  // dup'd head weights
};

__global__ void __launch_bounds__(32, 1)
lstm_fused_kernel(
    const float* __restrict__ x, const float* __restrict__ h0, const float* __restrict__ c0,
    const float* __restrict__ W_ih, const float* __restrict__ W_hh,
    const float* __restrict__ b_ih, const float* __restrict__ b_hh,
    const float* __restrict__ W_all, const float* __restrict__ b_all,
    const float* __restrict__ W_pos, const float* __restrict__ b_pos,
    const float* __restrict__ W_lv, const float* __restrict__ b_lv,
    float* __restrict__ out)
{
    __shared__ Smem sm;
    const int lane = threadIdx.x;
    const int s0 = blockIdx.x * NS;

    // ---- one-time init ----
    #pragma unroll
    for (int k = 0; k < NK; ++k) {
        sm.sWih[k][lane] = make_ulonglong2(
            pack2(W_ih[lane * FEAT + k],        W_ih[(32 + lane) * FEAT + k]),
            pack2(W_ih[(64 + lane) * FEAT + k], W_ih[(96 + lane) * FEAT + k]));
    }
    ull whh_if[HIDDEN], whh_go[HIDDEN];   // register-resident, shared by 8 samples
    #pragma unroll
    for (int k = 0; k < HIDDEN; ++k) {
        whh_if[k] = pack2(W_hh[lane * HIDDEN + k],        W_hh[(32 + lane) * HIDDEN + k]);
        whh_go[k] = pack2(W_hh[(64 + lane) * HIDDEN + k], W_hh[(96 + lane) * HIDDEN + k]);
    }
    // folded heads: wc = W_pos @ W_all, cb = W_pos @ b_all + b_pos
    float wc0 = 0.f, wc1 = 0.f, cb0 = b_pos[0], cb1 = b_pos[1];
    #pragma unroll
    for (int m = 0; m < HIDDEN; ++m) {
        const float wa = W_all[m * HIDDEN + lane];
        wc0 = fmaf(W_pos[m],      wa, wc0);
        wc1 = fmaf(W_pos[32 + m], wa, wc1);
        cb0 = fmaf(W_pos[m],      b_all[m], cb0);
        cb1 = fmaf(W_pos[32 + m], b_all[m], cb1);
    }
    sm.wcd0[lane] = dup2(wc0);
    sm.wcd1[lane] = dup2(wc1);
    sm.wcdl[lane] = dup2(W_lv[lane]);
    const float blv = b_lv[0];

    // Gate biases with W_ih[:,29]*1.0 folded in (mask bit == 1.0 on active steps;
    // inactive samples compute garbage gates, selected away below).
    const ull bias_if = pack2(b_ih[lane]      + b_hh[lane]      + W_ih[lane * FEAT + 29],
                              b_ih[32 + lane] + b_hh[32 + lane] + W_ih[(32 + lane) * FEAT + 29]);
    const ull bias_go = pack2(b_ih[64 + lane] + b_hh[64 + lane] + W_ih[(64 + lane) * FEAT + 29],
                              b_ih[96 + lane] + b_hh[96 + lane] + W_ih[(96 + lane) * FEAT + 29]);

    const float* xb = x + (size_t)s0 * TSF;

    float h[NS], c[NS];
    #pragma unroll
    for (int s = 0; s < NS; ++s) {
        h[s] = h0[(s0 + s) * HIDDEN + lane];
        c[s] = c0[(s0 + s) * HIDDEN + lane];
    }
    #pragma unroll
    for (int q = 0; q < 4; ++q) {
        sm.hq[0][lane][q] = make_ulonglong2(dup2(h[2 * q]), dup2(h[2 * q + 1]));
        sm.xq[0][lane][q] = make_ulonglong2(dup2(xb[(2 * q) * TSF + lane]),
                                            dup2(xb[(2 * q + 1) * TSF + lane]));
    }
    __syncwarp();

    float* pos_out = out;                                   // [B,T,2]
    float* lv_out  = out + (size_t)BATCH * TSTEPS * 2;      // [B,T,1]
    float* hT_out  = out + (size_t)BATCH * TSTEPS * 3;      // [1,B,H]
    float* cT_out  = hT_out + BATCH * HIDDEN;               // [1,B,H]

    for (int t = 0; t < TSTEPS; ++t) {
        const int bsel = t & 1;
        const int slot = t & (CHUNK - 1);

        // Unconditional prefetch (clamped at the tail; always in-bounds).
        const int tn = (t + 1 < TSTEPS) ? (t + 1) : t;
        const int o = tn * FEAT + lane;
        float xn[NS];
        #pragma unroll
        for (int s = 0; s < NS; ++s) xn[s] = xb[s * TSF + o];

        // Mask bits (dup'd entries at row 29).
        bool act[NS];
        #pragma unroll
        for (int q = 0; q < 4; ++q) {
            const ulonglong2 mq = sm.xq[bsel][29][q];
            act[2 * q]     = (unpack2(mq.x).x == 1.0f);
            act[2 * q + 1] = (unpack2(mq.y).x == 1.0f);
        }

        ull aif[NS], ago[NS];
        #pragma unroll
        for (int s = 0; s < NS; ++s) { aif[s] = bias_if; ago[s] = bias_go; }

        #pragma unroll
        for (int k = 0; k < NK; ++k) {
            const ulonglong2 w = sm.sWih[k][lane];
            #pragma unroll
            for (int q = 0; q < 4; ++q) {
                const ulonglong2 xk = sm.xq[bsel][k][q];
                aif[2 * q]     = fma2(xk.x, w.x, aif[2 * q]);
                ago[2 * q]     = fma2(xk.x, w.y, ago[2 * q]);
                aif[2 * q + 1] = fma2(xk.y, w.x, aif[2 * q + 1]);
                ago[2 * q + 1] = fma2(xk.y, w.y, ago[2 * q + 1]);
            }
        }
        #pragma unroll
        for (int k = 0; k < HIDDEN; ++k) {
            const ull wi = whh_if[k], wg = whh_go[k];
            #pragma unroll
            for (int q = 0; q < 4; ++q) {
                const ulonglong2 hk = sm.hq[bsel][k][q];
                aif[2 * q]     = fma2(hk.x, wi, aif[2 * q]);
                ago[2 * q]     = fma2(hk.x, wg, ago[2 * q]);
                aif[2 * q + 1] = fma2(hk.y, wi, aif[2 * q + 1]);
                ago[2 * q + 1] = fma2(hk.y, wg, ago[2 * q + 1]);
            }
        }

        float hs[NS];
        #pragma unroll
        for (int s = 0; s < NS; ++s) {
            const float2 g1 = unpack2(aif[s]), g2 = unpack2(ago[s]);
            const float cn = fmaf(sigf(g1.y), c[s], sigf(g1.x) * tanhap(g2.x));
            const float hn = sigf(g2.y) * tanhap(cn);
            c[s]  = act[s] ? cn : c[s];
            h[s]  = act[s] ? hn : h[s];
            hs[s] = act[s] ? hn : 0.f;
        }

        #pragma unroll
        for (int q = 0; q < 4; ++q) {
            sm.hq[bsel ^ 1][lane][q] = make_ulonglong2(dup2(h[2 * q]), dup2(h[2 * q + 1]));
            sm.xq[bsel ^ 1][lane][q] = make_ulonglong2(dup2(xn[2 * q]), dup2(xn[2 * q + 1]));
        }
        {
            // 16B-aligned: slot*HSTRIDE*8 ≡ 0 mod 16, lane*4*8 = 32B.
            ulonglong2* hrow = reinterpret_cast<ulonglong2*>(&sm.hist[slot][lane * 4]);
            hrow[0] = make_ulonglong2(pack2(hs[0], hs[1]), pack2(hs[2], hs[3]));
            hrow[1] = make_ulonglong2(pack2(hs[4], hs[5]), pack2(hs[6], hs[7]));
        }
        __syncwarp();

        // bulk head phase over the finished 16-step chunk
        if (slot == CHUNK - 1) {
            const int tt = lane & 15;
            const int prb = lane >> 4;
            #pragma unroll
            for (int half = 0; half < 2; ++half) {
                const int pr = prb + 2 * half;          // 0..3 -> sample pair (2pr, 2pr+1)
                const ull* hrow = &sm.hist[tt][pr];
                ull p0 = 0ULL, p1 = 0ULL, pl = 0ULL;
                #pragma unroll
                for (int j = 0; j < HIDDEN; ++j) {
                    const ull hv = hrow[j * 4];
                    p0 = fma2(hv, sm.wcd0[j], p0);
                    p1 = fma2(hv, sm.wcd1[j], p1);
                    pl = fma2(hv, sm.wcdl[j], pl);
                }
                const float2 q0 = unpack2(p0), q1 = unpack2(p1), ql = unpack2(pl);
                const int tg = t - (CHUNK - 1) + tt;
                const size_t oA = (size_t)(s0 + 2 * pr) * TSTEPS + tg;
                const size_t oB = oA + TSTEPS;
                reinterpret_cast<float2*>(pos_out)[oA] = make_float2(q0.x + cb0, q1.x + cb1);
                reinterpret_cast<float2*>(pos_out)[oB] = make_float2(q0.y + cb0, q1.y + cb1);
                lv_out[oA] = sigf(ql.x + blv);
                lv_out[oB] = sigf(ql.y + blv);
            }
            __syncwarp();
        }
    }

    #pragma unroll
    for (int s = 0; s < NS; ++s) {
        hT_out[(s0 + s) * HIDDEN + lane] = h[s];
        cT_out[(s0 + s) * HIDDEN + lane] = c[s];
    }
}

extern "C" void kernel_launch(void* const* d_in, const int* in_sizes, int n_in,
                              void* d_out, int out_size)
{
    const float* x    = (const float*)d_in[0];
    const float* h0   = (const float*)d_in[1];
    const float* c0   = (const float*)d_in[2];
    const float* W_ih = (const float*)d_in[3];
    const float* W_hh = (const float*)d_in[4];
    const float* b_ih = (const float*)d_in[5];
    const float* b_hh = (const float*)d_in[6];
    const float* W_all= (const float*)d_in[7];
    const float* b_all= (const float*)d_in[8];
    const float* W_pos= (const float*)d_in[9];
    const float* b_pos= (const float*)d_in[10];
    const float* W_lv = (const float*)d_in[11];
    const float* b_lv = (const float*)d_in[12];
    float* out = (float*)d_out;

    lstm_fused_kernel<<<BATCH / NS, 32>>>(x, h0, c0, W_ih, W_hh, b_ih, b_hh,
                                          W_all, b_all, W_pos, b_pos, W_lv, b_lv, out);
}